// round 15
// baseline (speedup 1.0000x reference)
#include <cuda_runtime.h>
#include <cuda_fp16.h>
#include <cstdint>
#include <math.h>

#define BATCH   8
#define SEQ     1024
#define DIM     768
#define HEADS   12
#define DHEAD   64
#define INNER   768
#define NQKV    2304
#define MROWS   8192
#define SC_LOG2E 0.1803368801111244f
#define ONES_H2 0x3C003C00u   // fp16 1.0 x2

// ---------------------------------------------------------------------------
// Persistent fp16 scratch (all single fp16; error budget fixed at ~6.5e-4)
// ---------------------------------------------------------------------------
__device__ __half g_Xs [MROWS*DIM];
__device__ __half g_WQs[DIM*NQKV];
__device__ __half g_WOs[INNER*DIM];
__device__ __half g_Qs [BATCH*HEADS*SEQ*DHEAD];
__device__ __half g_Ks [BATCH*HEADS*SEQ*DHEAD];
__device__ __half g_Vs [BATCH*HEADS*SEQ*DHEAD];
__device__ __half g_AOs[MROWS*INNER];

// ---------------------------------------------------------------------------
// Helpers
// ---------------------------------------------------------------------------
__device__ __forceinline__ uint32_t smem_u32(const void* p) {
    uint32_t a;
    asm("{ .reg .u64 t; cvta.to.shared.u64 t, %1; cvt.u32.u64 %0, t; }" : "=r"(a) : "l"(p));
    return a;
}
__device__ __forceinline__ void ldsm4(uint32_t addr, uint32_t* r) {
    asm volatile("ldmatrix.sync.aligned.m8n8.x4.shared.b16 {%0,%1,%2,%3}, [%4];"
                 : "=r"(r[0]), "=r"(r[1]), "=r"(r[2]), "=r"(r[3]) : "r"(addr));
}
__device__ __forceinline__ void ldsm4t(uint32_t addr, uint32_t* r) {
    asm volatile("ldmatrix.sync.aligned.m8n8.x4.trans.shared.b16 {%0,%1,%2,%3}, [%4];"
                 : "=r"(r[0]), "=r"(r[1]), "=r"(r[2]), "=r"(r[3]) : "r"(addr));
}
__device__ __forceinline__ void mma16816(float* c, const uint32_t* a, uint32_t b0, uint32_t b1) {
    asm volatile("mma.sync.aligned.m16n8k16.row.col.f32.f16.f16.f32 "
                 "{%0,%1,%2,%3}, {%4,%5,%6,%7}, {%8,%9}, {%0,%1,%2,%3};"
                 : "+f"(c[0]), "+f"(c[1]), "+f"(c[2]), "+f"(c[3])
                 : "r"(a[0]), "r"(a[1]), "r"(a[2]), "r"(a[3]), "r"(b0), "r"(b1));
}
__device__ __forceinline__ float fast_exp2(float x) {
    float y;
    asm("ex2.approx.f32 %0, %1;" : "=f"(y) : "f"(x));
    return y;
}
__device__ __forceinline__ void cpa16(uint32_t dst, const void* src) {
    asm volatile("cp.async.cg.shared.global [%0], [%1], 16;" :: "r"(dst), "l"(src));
}
#define CP_COMMIT() asm volatile("cp.async.commit_group;" ::: "memory")
#define CP_WAIT0()  asm volatile("cp.async.wait_group 0;" ::: "memory")

__device__ __forceinline__ uint32_t pack_h2(float x, float y) {
    __half2 h = __halves2half2(__float2half_rn(x), __float2half_rn(y));
    return *reinterpret_cast<uint32_t*>(&h);
}

// ---------------------------------------------------------------------------
// Merged pre-convert: fp32 -> fp16 for X, Wqkv, Wout in one launch.
// ---------------------------------------------------------------------------
#define N_X  (MROWS*DIM)
#define N_WQ (DIM*NQKV)
#define N_WO (INNER*DIM)

__global__ void cvt_all(const float* __restrict__ x,
                        const float* __restrict__ wq,
                        const float* __restrict__ wo)
{
    const int i = (blockIdx.x * blockDim.x + threadIdx.x) * 4;
    const float* src;
    __half* dst;
    int j;
    if (i < N_X)                { src = x;  dst = g_Xs;  j = i; }
    else if (i < N_X + N_WQ)    { src = wq; dst = g_WQs; j = i - N_X; }
    else if (i < N_X+N_WQ+N_WO) { src = wo; dst = g_WOs; j = i - N_X - N_WQ; }
    else return;
    float4 v = *(const float4*)(src + j);
    *(__half2*)(dst + j)     = __halves2half2(__float2half_rn(v.x), __float2half_rn(v.y));
    *(__half2*)(dst + j + 2) = __halves2half2(__float2half_rn(v.z), __float2half_rn(v.w));
}

// ---------------------------------------------------------------------------
// GEMM: single-pass fp16, K-chunk 32, 4-stage pipeline, barrier per PAIR of
// chunks (wait0 -> barrier -> prefetch pair+1 -> compute c, c+1), 2 CTAs/SM.
// MODE 0: M-tile 128 (X @ Wqkv -> Q(scaled)/K/V).  8 warps 4m x 2n.
// MODE 1: M-tile 64  (AO @ Wout + bias -> fp32).   8 warps 2m x 4n.
// ---------------------------------------------------------------------------
#define G_NCHUNK 24

template<int MODE>
__global__ void __launch_bounds__(256, 2)
gemm_tc(const float* __restrict__ bias, float* __restrict__ out)
{
    constexpr int MT   = (MODE == 0) ? 128 : 64;   // M tile
    constexpr int NPW  = (MODE == 0) ? 64  : 32;   // N cols per warp
    constexpr int NTC  = NPW / 8;                  // n8 tiles per warp
    constexpr int NPB  = NPW / 16;                 // ldsm4t per ks per warp
    constexpr int BOFF = MT * 80;                  // B area offset in stage
    constexpr int STG  = BOFF + 8704;              // stage bytes

    extern __shared__ char smem[];
    const uint32_t sb = smem_u32(smem);
    const int tid  = threadIdx.x;
    const int lane = tid & 31;
    const int wid  = tid >> 5;
    const int wm   = (MODE == 0) ? (wid & 3) : (wid & 1);
    const int wn   = (MODE == 0) ? (wid >> 2) : (wid >> 1);
    const int bx = blockIdx.x, by = blockIdx.y;

    const __half* As = (MODE == 0) ? g_Xs  : g_AOs;
    const __half* Bs = (MODE == 0) ? g_WQs : g_WOs;
    const int ldb = (MODE == 0) ? NQKV : DIM;

    float acc[2][NTC][4];
    #pragma unroll
    for (int i = 0; i < 2; i++)
        #pragma unroll
        for (int j = 0; j < NTC; j++)
            #pragma unroll
            for (int k = 0; k < 4; k++) acc[i][j][k] = 0.f;

    const int lrow = lane & 15;
    const int lc16 = (lane >> 4) * 16;
    const uint32_t aA = sb + (uint32_t)((wm*32 + lrow)*80) + lc16;
    const uint32_t aB = sb + BOFF + (uint32_t)(lrow*272) + (uint32_t)(wn*NPW*2) + lc16;

    auto prefetch = [&](int ch, int st) {
        const int k0 = ch * 32;
        const uint32_t sa = sb + (uint32_t)st * STG;
        #pragma unroll
        for (int i = tid; i < MT*4; i += 256) {
            const int row = i >> 2, seg = i & 3;
            cpa16(sa + row*80 + seg*16,
                  As + (size_t)(by*MT + row)*768 + k0 + seg*8);
        }
        #pragma unroll
        for (int i = tid; i < 512; i += 256) {
            const int row = i >> 4, seg = i & 15;
            cpa16(sa + BOFF + row*272 + seg*16,
                  Bs + (size_t)(k0 + row)*ldb + bx*128 + seg*8);
        }
    };

    prefetch(0, 0); CP_COMMIT();
    prefetch(1, 1); CP_COMMIT();

    for (int p = 0; p < G_NCHUNK/2; p++) {
        const int c = 2*p;
        CP_WAIT0();        // this thread's copies for chunks c, c+1 complete
        __syncthreads();   // all threads' copies visible; prior pair's reads done
        if (c + 2 < G_NCHUNK) {
            prefetch(c + 2, (c + 2) & 3); CP_COMMIT();
            prefetch(c + 3, (c + 3) & 3); CP_COMMIT();
        }
        #pragma unroll
        for (int cc = 0; cc < 2; cc++) {
            const uint32_t so = (uint32_t)((c + cc) & 3) * STG;
            #pragma unroll
            for (int ks = 0; ks < 2; ks++) {
                uint32_t ah[2][4];
                ldsm4(aA + so + ks*32,         ah[0]);
                ldsm4(aA + so + 16*80 + ks*32, ah[1]);
                uint32_t bh[NPB][4];
                #pragma unroll
                for (int np = 0; np < NPB; np++)
                    ldsm4t(aB + so + ks*4352 + np*32, bh[np]);
                #pragma unroll
                for (int np = 0; np < NPB; np++)
                    #pragma unroll
                    for (int mt = 0; mt < 2; mt++) {
                        mma16816(acc[mt][np*2+0], ah[mt], bh[np][0], bh[np][1]);
                        mma16816(acc[mt][np*2+1], ah[mt], bh[np][2], bh[np][3]);
                    }
            }
        }
    }

    // Epilogue
    #pragma unroll
    for (int mt = 0; mt < 2; mt++) {
        const int row0 = by*MT + wm*32 + mt*16 + (lane >> 2);
        #pragma unroll
        for (int nt = 0; nt < NTC; nt++) {
            const int col = bx*128 + wn*NPW + nt*8 + (lane & 3)*2;
            if (MODE == 0) {
                const int sel = col / INNER;
                const int cr = col - sel*INNER;
                const int h = cr >> 6, d = cr & 63;
                __half* dst = (sel == 0) ? g_Qs : (sel == 1) ? g_Ks : g_Vs;
                const float sc = (sel == 0) ? SC_LOG2E : 1.f;
                #pragma unroll
                for (int rr = 0; rr < 2; rr++) {
                    const int r = row0 + rr*8;
                    const int b = r >> 10, nn = r & 1023;
                    const size_t idx = (size_t)(((b*HEADS + h) << 10) + nn)*DHEAD + d;
                    *(__half2*)(dst + idx) =
                        __halves2half2(__float2half_rn(acc[mt][nt][rr*2+0]*sc),
                                       __float2half_rn(acc[mt][nt][rr*2+1]*sc));
                }
            } else {
                const float b0 = bias[col], b1 = bias[col+1];
                *(float2*)&out[(size_t)row0*DIM + col] =
                    make_float2(acc[mt][nt][0] + b0, acc[mt][nt][1] + b1);
                *(float2*)&out[(size_t)(row0+8)*DIM + col] =
                    make_float2(acc[mt][nt][2] + b0, acc[mt][nt][3] + b1);
            }
        }
    }
}

#define G_SMEM0 (4*(128*80 + 8704))   // 75776
#define G_SMEM1 (4*(64*80 + 8704))    // 55296

// ---------------------------------------------------------------------------
// Attention: single-pass, P-in-registers, rowsum via ones-MMA,
// 4-stage KV pipeline, barrier per PAIR of chunks, 2 CTAs/SM.
// 8 warps x 16 q rows; warp covers all 64 keys and all 64 d.
// ---------------------------------------------------------------------------
#define A_Q   0
#define A_KV0 18432
#define A_KSo 0
#define A_VSo 9216
#define A_KVSTAGE 18432
#define A_SMEM_BYTES (18432 + 4*A_KVSTAGE)   // 92160
#define A_NCHUNK 16

__global__ void __launch_bounds__(256, 2)
attn_tc()
{
    extern __shared__ char smem[];
    const uint32_t sb = smem_u32(smem);
    const int tid  = threadIdx.x;
    const int lane = tid & 31;
    const int wid  = tid >> 5;
    const int bh = blockIdx.y;
    const int q0 = blockIdx.x * 128;

    const size_t base = (size_t)bh * SEQ * DHEAD;

    auto prefetchKV = [&](int c, int st) {
        const size_t g0 = base + (size_t)c*64*DHEAD;
        const uint32_t sa = sb + A_KV0 + (uint32_t)st * A_KVSTAGE;
        #pragma unroll
        for (int i = tid; i < 512; i += 256) {
            const int row = i >> 3, seg = i & 7;
            const uint32_t d = sa + row*144 + seg*16;
            const size_t g = g0 + row*64 + seg*8;
            cpa16(d + A_KSo, g_Ks + g);
            cpa16(d + A_VSo, g_Vs + g);
        }
    };

    // group 0 = Q + KV chunk 0, group 1 = KV chunk 1
    #pragma unroll
    for (int i = tid; i < 1024; i += 256) {
        const int row = i >> 3, seg = i & 7;
        cpa16(sb + A_Q + row*144 + seg*16,
              g_Qs + base + (size_t)(q0 + row)*DHEAD + seg*8);
    }
    prefetchKV(0, 0); CP_COMMIT();
    prefetchKV(1, 1); CP_COMMIT();

    float o[8][4];
    #pragma unroll
    for (int j = 0; j < 8; j++)
        #pragma unroll
        for (int k = 0; k < 4; k++) o[j][k] = 0.f;
    float rs[4] = {0.f, 0.f, 0.f, 0.f};

    const int lrow = lane & 15;
    const int lc16 = (lane >> 4) * 16;
    const uint32_t aQ = sb + A_Q   + (uint32_t)((wid*16 + lrow)*144) + lc16;
    const uint32_t aK = sb + A_KV0 + A_KSo + (uint32_t)(lrow*144) + lc16;
    const uint32_t aV = sb + A_KV0 + A_VSo + (uint32_t)(lrow*144) + lc16;

    for (int p = 0; p < A_NCHUNK/2; p++) {
        const int c = 2*p;
        CP_WAIT0();
        __syncthreads();
        if (c + 2 < A_NCHUNK) {
            prefetchKV(c + 2, (c + 2) & 3); CP_COMMIT();
            prefetchKV(c + 3, (c + 3) & 3); CP_COMMIT();
        }

        #pragma unroll
        for (int cc = 0; cc < 2; cc++) {
            const uint32_t so = (uint32_t)((c + cc) & 3) * A_KVSTAGE;

            // ---- S = Q @ K^T ----
            float s[8][4];
            #pragma unroll
            for (int j = 0; j < 8; j++)
                #pragma unroll
                for (int k = 0; k < 4; k++) s[j][k] = 0.f;

            #pragma unroll
            for (int ks = 0; ks < 4; ks++) {
                uint32_t qh[4];
                ldsm4(aQ + ks*32, qh);
                uint32_t kh[4][4];
                #pragma unroll
                for (int np = 0; np < 4; np++)
                    ldsm4(aK + so + np*16*144 + ks*32, kh[np]);
                // non-trans pairing: {r0,r2} / {r1,r3}
                #pragma unroll
                for (int np = 0; np < 4; np++) {
                    mma16816(s[np*2+0], qh, kh[np][0], kh[np][2]);
                    mma16816(s[np*2+1], qh, kh[np][1], kh[np][3]);
                }
            }

            // ---- P = 2^S -> fp16 A-fragments; rowsum via ones-MMA ----
            uint32_t pa[4][4];
            #pragma unroll
            for (int kf = 0; kf < 4; kf++) {
                const int t0 = 2*kf, t1 = 2*kf + 1;
                const float e0 = fast_exp2(s[t0][0]);
                const float e1 = fast_exp2(s[t0][1]);
                const float e2 = fast_exp2(s[t0][2]);
                const float e3 = fast_exp2(s[t0][3]);
                const float f0 = fast_exp2(s[t1][0]);
                const float f1 = fast_exp2(s[t1][1]);
                const float f2 = fast_exp2(s[t1][2]);
                const float f3 = fast_exp2(s[t1][3]);
                pa[kf][0] = pack_h2(e0, e1);
                pa[kf][1] = pack_h2(e2, e3);
                pa[kf][2] = pack_h2(f0, f1);
                pa[kf][3] = pack_h2(f2, f3);
                mma16816(rs, pa[kf], ONES_H2, ONES_H2);
            }

            // ---- O += P @ V ----
            #pragma unroll
            for (int kf = 0; kf < 4; kf++) {
                uint32_t vh[4][4];
                #pragma unroll
                for (int np = 0; np < 4; np++)
                    ldsm4t(aV + so + kf*16*144 + np*32, vh[np]);
                // trans pairing: {r0,r1} / {r2,r3}
                #pragma unroll
                for (int np = 0; np < 4; np++) {
                    mma16816(o[np*2+0], pa[kf], vh[np][0], vh[np][1]);
                    mma16816(o[np*2+1], pa[kf], vh[np][2], vh[np][3]);
                }
            }
        }
    }

    // rs[0] = rowsum(row), rs[2] = rowsum(row+8)
    const float inv0 = 1.f / rs[0];
    const float inv1 = 1.f / rs[2];

    // Normalize + fp16 AO store
    const int b = bh / HEADS;
    const int h = bh - b*HEADS;
    const int row0 = q0 + wid*16 + (lane >> 2);
    #pragma unroll
    for (int nt = 0; nt < 8; nt++) {
        const int d = nt*8 + (lane & 3)*2;
        const size_t i0 = (size_t)(b*SEQ + row0)*INNER + h*DHEAD + d;
        const size_t i1 = (size_t)(b*SEQ + row0 + 8)*INNER + h*DHEAD + d;
        *(__half2*)(g_AOs + i0) =
            __halves2half2(__float2half_rn(o[nt][0]*inv0), __float2half_rn(o[nt][1]*inv0));
        *(__half2*)(g_AOs + i1) =
            __halves2half2(__float2half_rn(o[nt][2]*inv1), __float2half_rn(o[nt][3]*inv1));
    }
}

// ---------------------------------------------------------------------------
// Launch
// ---------------------------------------------------------------------------
extern "C" void kernel_launch(void* const* d_in, const int* in_sizes, int n_in,
                              void* d_out, int out_size)
{
    const float* x     = (const float*)d_in[0];
    const float* w_qkv = (const float*)d_in[1];
    const float* w_out = (const float*)d_in[2];
    const float* b_out = (const float*)d_in[3];
    float* out = (float*)d_out;

    cudaFuncSetAttribute(gemm_tc<0>, cudaFuncAttributeMaxDynamicSharedMemorySize, G_SMEM0);
    cudaFuncSetAttribute(gemm_tc<1>, cudaFuncAttributeMaxDynamicSharedMemorySize, G_SMEM1);
    cudaFuncSetAttribute(attn_tc,    cudaFuncAttributeMaxDynamicSharedMemorySize, A_SMEM_BYTES);

    cvt_all<<<(N_X + N_WQ + N_WO)/1024, 256>>>(x, w_qkv, w_out);

    dim3 g1(NQKV/128, MROWS/128);   // 18 x 64
    gemm_tc<0><<<g1, 256, G_SMEM0>>>(nullptr, nullptr);

    dim3 g2(SEQ/128, BATCH*HEADS);  // 8 x 96
    attn_tc<<<g2, 256, A_SMEM_BYTES>>>();

    dim3 g3(DIM/128, MROWS/64);     // 6 x 128 (M-tile 64: 768 CTAs, no tail wave)
    gemm_tc<1><<<g3, 256, G_SMEM1>>>(b_out, out);
}

// round 16
// speedup vs baseline: 1.0324x; 1.0324x over previous
#include <cuda_runtime.h>
#include <cuda_fp16.h>
#include <cstdint>
#include <math.h>

#define BATCH   8
#define SEQ     1024
#define DIM     768
#define HEADS   12
#define DHEAD   64
#define INNER   768
#define NQKV    2304
#define MROWS   8192
#define SC_LOG2E 0.1803368801111244f
#define ONES_H2 0x3C003C00u   // fp16 1.0 x2

// ---------------------------------------------------------------------------
// Persistent fp16 scratch (all single fp16; error budget fixed at ~6.5e-4)
// ---------------------------------------------------------------------------
__device__ __half g_Xs [MROWS*DIM];
__device__ __half g_WQs[DIM*NQKV];
__device__ __half g_WOs[INNER*DIM];
__device__ __half g_Qs [BATCH*HEADS*SEQ*DHEAD];
__device__ __half g_Ks [BATCH*HEADS*SEQ*DHEAD];
__device__ __half g_Vs [BATCH*HEADS*SEQ*DHEAD];
__device__ __half g_AOs[MROWS*INNER];

// ---------------------------------------------------------------------------
// Helpers
// ---------------------------------------------------------------------------
__device__ __forceinline__ uint32_t smem_u32(const void* p) {
    uint32_t a;
    asm("{ .reg .u64 t; cvta.to.shared.u64 t, %1; cvt.u32.u64 %0, t; }" : "=r"(a) : "l"(p));
    return a;
}
__device__ __forceinline__ void ldsm4(uint32_t addr, uint32_t* r) {
    asm volatile("ldmatrix.sync.aligned.m8n8.x4.shared.b16 {%0,%1,%2,%3}, [%4];"
                 : "=r"(r[0]), "=r"(r[1]), "=r"(r[2]), "=r"(r[3]) : "r"(addr));
}
__device__ __forceinline__ void ldsm4t(uint32_t addr, uint32_t* r) {
    asm volatile("ldmatrix.sync.aligned.m8n8.x4.trans.shared.b16 {%0,%1,%2,%3}, [%4];"
                 : "=r"(r[0]), "=r"(r[1]), "=r"(r[2]), "=r"(r[3]) : "r"(addr));
}
__device__ __forceinline__ void mma16816(float* c, const uint32_t* a, uint32_t b0, uint32_t b1) {
    asm volatile("mma.sync.aligned.m16n8k16.row.col.f32.f16.f16.f32 "
                 "{%0,%1,%2,%3}, {%4,%5,%6,%7}, {%8,%9}, {%0,%1,%2,%3};"
                 : "+f"(c[0]), "+f"(c[1]), "+f"(c[2]), "+f"(c[3])
                 : "r"(a[0]), "r"(a[1]), "r"(a[2]), "r"(a[3]), "r"(b0), "r"(b1));
}
__device__ __forceinline__ float fast_exp2(float x) {
    float y;
    asm("ex2.approx.f32 %0, %1;" : "=f"(y) : "f"(x));
    return y;
}
__device__ __forceinline__ void cpa16(uint32_t dst, const void* src) {
    asm volatile("cp.async.cg.shared.global [%0], [%1], 16;" :: "r"(dst), "l"(src));
}
#define CP_COMMIT() asm volatile("cp.async.commit_group;" ::: "memory")
#define CP_WAIT0()  asm volatile("cp.async.wait_group 0;" ::: "memory")

__device__ __forceinline__ uint32_t pack_h2(float x, float y) {
    __half2 h = __halves2half2(__float2half_rn(x), __float2half_rn(y));
    return *reinterpret_cast<uint32_t*>(&h);
}

// ---------------------------------------------------------------------------
// Merged pre-convert: fp32 -> fp16 for X, Wqkv, Wout in one launch.
// ---------------------------------------------------------------------------
#define N_X  (MROWS*DIM)
#define N_WQ (DIM*NQKV)
#define N_WO (INNER*DIM)

__global__ void cvt_all(const float* __restrict__ x,
                        const float* __restrict__ wq,
                        const float* __restrict__ wo)
{
    const int i = (blockIdx.x * blockDim.x + threadIdx.x) * 4;
    const float* src;
    __half* dst;
    int j;
    if (i < N_X)                { src = x;  dst = g_Xs;  j = i; }
    else if (i < N_X + N_WQ)    { src = wq; dst = g_WQs; j = i - N_X; }
    else if (i < N_X+N_WQ+N_WO) { src = wo; dst = g_WOs; j = i - N_X - N_WQ; }
    else return;
    float4 v = *(const float4*)(src + j);
    *(__half2*)(dst + j)     = __halves2half2(__float2half_rn(v.x), __float2half_rn(v.y));
    *(__half2*)(dst + j + 2) = __halves2half2(__float2half_rn(v.z), __float2half_rn(v.w));
}

// ---------------------------------------------------------------------------
// GEMM: single-pass fp16, 128x128 tile, K-chunk 32, 4-stage pipeline,
// barrier per PAIR of chunks, 2 CTAs/SM. 8 warps 4m x 2n.
// MODE 0: X @ Wqkv -> Q(scaled)/K/V fp16.  MODE 1: AO @ Wout + bias -> fp32.
// ---------------------------------------------------------------------------
#define G_A   0
#define G_B   10240
#define G_STAGE 18944
#define G_SMEM_BYTES (4*G_STAGE)   // 75776
#define G_NCHUNK 24

template<int MODE>
__global__ void __launch_bounds__(256, 2)
gemm_tc(const float* __restrict__ bias, float* __restrict__ out)
{
    extern __shared__ char smem[];
    const uint32_t sb = smem_u32(smem);
    const int tid  = threadIdx.x;
    const int lane = tid & 31;
    const int wid  = tid >> 5;
    const int wm   = wid & 3;
    const int wn   = wid >> 2;
    const int bx = blockIdx.x, by = blockIdx.y;

    const __half* As = (MODE == 0) ? g_Xs  : g_AOs;
    const __half* Bs = (MODE == 0) ? g_WQs : g_WOs;
    const int ldb = (MODE == 0) ? NQKV : DIM;

    float acc[2][8][4];
    #pragma unroll
    for (int i = 0; i < 2; i++)
        #pragma unroll
        for (int j = 0; j < 8; j++)
            #pragma unroll
            for (int k = 0; k < 4; k++) acc[i][j][k] = 0.f;

    const int lrow = lane & 15;
    const int lc16 = (lane >> 4) * 16;
    const uint32_t aA = sb + G_A + (uint32_t)((wm*32 + lrow)*80) + lc16;
    const uint32_t aB = sb + G_B + (uint32_t)(lrow*272) + (uint32_t)(wn*128) + lc16;

    auto prefetch = [&](int ch, int st) {
        const int k0 = ch * 32;
        const uint32_t sa = sb + (uint32_t)st * G_STAGE;
        #pragma unroll
        for (int i = tid; i < 512; i += 256) {
            const int row = i >> 2, seg = i & 3;
            cpa16(sa + G_A + row*80 + seg*16,
                  As + (size_t)(by*128 + row)*768 + k0 + seg*8);
        }
        #pragma unroll
        for (int i = tid; i < 512; i += 256) {
            const int row = i >> 4, seg = i & 15;
            cpa16(sa + G_B + row*272 + seg*16,
                  Bs + (size_t)(k0 + row)*ldb + bx*128 + seg*8);
        }
    };

    prefetch(0, 0); CP_COMMIT();
    prefetch(1, 1); CP_COMMIT();

    for (int p = 0; p < G_NCHUNK/2; p++) {
        const int c = 2*p;
        CP_WAIT0();        // this thread's copies for chunks c, c+1 complete
        __syncthreads();   // all threads' copies visible; prior pair's reads done
        if (c + 2 < G_NCHUNK) {
            prefetch(c + 2, (c + 2) & 3); CP_COMMIT();
            prefetch(c + 3, (c + 3) & 3); CP_COMMIT();
        }
        #pragma unroll
        for (int cc = 0; cc < 2; cc++) {
            const uint32_t so = (uint32_t)((c + cc) & 3) * G_STAGE;
            #pragma unroll
            for (int ks = 0; ks < 2; ks++) {
                uint32_t ah[2][4];
                ldsm4(aA + so + ks*32,         ah[0]);
                ldsm4(aA + so + 16*80 + ks*32, ah[1]);
                uint32_t bh[4][4];
                #pragma unroll
                for (int np = 0; np < 4; np++)
                    ldsm4t(aB + so + ks*4352 + np*32, bh[np]);
                #pragma unroll
                for (int np = 0; np < 4; np++)
                    #pragma unroll
                    for (int mt = 0; mt < 2; mt++) {
                        mma16816(acc[mt][np*2+0], ah[mt], bh[np][0], bh[np][1]);
                        mma16816(acc[mt][np*2+1], ah[mt], bh[np][2], bh[np][3]);
                    }
            }
        }
    }

    // Epilogue
    #pragma unroll
    for (int mt = 0; mt < 2; mt++) {
        const int row0 = by*128 + wm*32 + mt*16 + (lane >> 2);
        #pragma unroll
        for (int nt = 0; nt < 8; nt++) {
            const int col = bx*128 + wn*64 + nt*8 + (lane & 3)*2;
            if (MODE == 0) {
                const int sel = col / INNER;
                const int cr = col - sel*INNER;
                const int h = cr >> 6, d = cr & 63;
                __half* dst = (sel == 0) ? g_Qs : (sel == 1) ? g_Ks : g_Vs;
                const float sc = (sel == 0) ? SC_LOG2E : 1.f;
                #pragma unroll
                for (int rr = 0; rr < 2; rr++) {
                    const int r = row0 + rr*8;
                    const int b = r >> 10, nn = r & 1023;
                    const size_t idx = (size_t)(((b*HEADS + h) << 10) + nn)*DHEAD + d;
                    *(__half2*)(dst + idx) =
                        __halves2half2(__float2half_rn(acc[mt][nt][rr*2+0]*sc),
                                       __float2half_rn(acc[mt][nt][rr*2+1]*sc));
                }
            } else {
                const float b0 = bias[col], b1 = bias[col+1];
                *(float2*)&out[(size_t)row0*DIM + col] =
                    make_float2(acc[mt][nt][0] + b0, acc[mt][nt][1] + b1);
                *(float2*)&out[(size_t)(row0+8)*DIM + col] =
                    make_float2(acc[mt][nt][2] + b0, acc[mt][nt][3] + b1);
            }
        }
    }
}

// ---------------------------------------------------------------------------
// Attention: single-pass, P-in-registers, rowsum via ones-MMA,
// Q fragments hoisted out of the chunk loop (chunk-invariant),
// 4-stage KV pipeline, barrier per PAIR of chunks, 2 CTAs/SM.
// ---------------------------------------------------------------------------
#define A_Q   0
#define A_KV0 18432
#define A_KSo 0
#define A_VSo 9216
#define A_KVSTAGE 18432
#define A_SMEM_BYTES (18432 + 4*A_KVSTAGE)   // 92160
#define A_NCHUNK 16

__global__ void __launch_bounds__(256, 2)
attn_tc()
{
    extern __shared__ char smem[];
    const uint32_t sb = smem_u32(smem);
    const int tid  = threadIdx.x;
    const int lane = tid & 31;
    const int wid  = tid >> 5;
    const int bh = blockIdx.y;
    const int q0 = blockIdx.x * 128;

    const size_t base = (size_t)bh * SEQ * DHEAD;

    auto prefetchKV = [&](int c, int st) {
        const size_t g0 = base + (size_t)c*64*DHEAD;
        const uint32_t sa = sb + A_KV0 + (uint32_t)st * A_KVSTAGE;
        #pragma unroll
        for (int i = tid; i < 512; i += 256) {
            const int row = i >> 3, seg = i & 7;
            const uint32_t d = sa + row*144 + seg*16;
            const size_t g = g0 + row*64 + seg*8;
            cpa16(d + A_KSo, g_Ks + g);
            cpa16(d + A_VSo, g_Vs + g);
        }
    };

    // group 0 = Q + KV chunk 0, group 1 = KV chunk 1
    #pragma unroll
    for (int i = tid; i < 1024; i += 256) {
        const int row = i >> 3, seg = i & 7;
        cpa16(sb + A_Q + row*144 + seg*16,
              g_Qs + base + (size_t)(q0 + row)*DHEAD + seg*8);
    }
    prefetchKV(0, 0); CP_COMMIT();
    prefetchKV(1, 1); CP_COMMIT();

    float o[8][4];
    #pragma unroll
    for (int j = 0; j < 8; j++)
        #pragma unroll
        for (int k = 0; k < 4; k++) o[j][k] = 0.f;
    float rs[4] = {0.f, 0.f, 0.f, 0.f};

    const int lrow = lane & 15;
    const int lc16 = (lane >> 4) * 16;
    const uint32_t aQ = sb + A_Q   + (uint32_t)((wid*16 + lrow)*144) + lc16;
    const uint32_t aK = sb + A_KV0 + A_KSo + (uint32_t)(lrow*144) + lc16;
    const uint32_t aV = sb + A_KV0 + A_VSo + (uint32_t)(lrow*144) + lc16;

    uint32_t qh[4][4];     // hoisted Q fragments (chunk-invariant)
    bool q_loaded = false;

    for (int p = 0; p < A_NCHUNK/2; p++) {
        const int c = 2*p;
        CP_WAIT0();
        __syncthreads();
        if (c + 2 < A_NCHUNK) {
            prefetchKV(c + 2, (c + 2) & 3); CP_COMMIT();
            prefetchKV(c + 3, (c + 3) & 3); CP_COMMIT();
        }
        if (!q_loaded) {   // first pair: Q (group 0) is now resident
            #pragma unroll
            for (int ks = 0; ks < 4; ks++)
                ldsm4(aQ + ks*32, qh[ks]);
            q_loaded = true;
        }

        #pragma unroll
        for (int cc = 0; cc < 2; cc++) {
            const uint32_t so = (uint32_t)((c + cc) & 3) * A_KVSTAGE;

            // ---- S = Q @ K^T ----
            float s[8][4];
            #pragma unroll
            for (int j = 0; j < 8; j++)
                #pragma unroll
                for (int k = 0; k < 4; k++) s[j][k] = 0.f;

            #pragma unroll
            for (int ks = 0; ks < 4; ks++) {
                uint32_t kh[4][4];
                #pragma unroll
                for (int np = 0; np < 4; np++)
                    ldsm4(aK + so + np*16*144 + ks*32, kh[np]);
                // non-trans pairing: {r0,r2} / {r1,r3}
                #pragma unroll
                for (int np = 0; np < 4; np++) {
                    mma16816(s[np*2+0], qh[ks], kh[np][0], kh[np][2]);
                    mma16816(s[np*2+1], qh[ks], kh[np][1], kh[np][3]);
                }
            }

            // ---- P = 2^S -> fp16 A-fragments; rowsum via ones-MMA ----
            uint32_t pa[4][4];
            #pragma unroll
            for (int kf = 0; kf < 4; kf++) {
                const int t0 = 2*kf, t1 = 2*kf + 1;
                const float e0 = fast_exp2(s[t0][0]);
                const float e1 = fast_exp2(s[t0][1]);
                const float e2 = fast_exp2(s[t0][2]);
                const float e3 = fast_exp2(s[t0][3]);
                const float f0 = fast_exp2(s[t1][0]);
                const float f1 = fast_exp2(s[t1][1]);
                const float f2 = fast_exp2(s[t1][2]);
                const float f3 = fast_exp2(s[t1][3]);
                pa[kf][0] = pack_h2(e0, e1);
                pa[kf][1] = pack_h2(e2, e3);
                pa[kf][2] = pack_h2(f0, f1);
                pa[kf][3] = pack_h2(f2, f3);
                mma16816(rs, pa[kf], ONES_H2, ONES_H2);
            }

            // ---- O += P @ V ----
            #pragma unroll
            for (int kf = 0; kf < 4; kf++) {
                uint32_t vh[4][4];
                #pragma unroll
                for (int np = 0; np < 4; np++)
                    ldsm4t(aV + so + kf*16*144 + np*32, vh[np]);
                // trans pairing: {r0,r1} / {r2,r3}
                #pragma unroll
                for (int np = 0; np < 4; np++) {
                    mma16816(o[np*2+0], pa[kf], vh[np][0], vh[np][1]);
                    mma16816(o[np*2+1], pa[kf], vh[np][2], vh[np][3]);
                }
            }
        }
    }

    // rs[0] = rowsum(row), rs[2] = rowsum(row+8)
    const float inv0 = 1.f / rs[0];
    const float inv1 = 1.f / rs[2];

    // Normalize + fp16 AO store
    const int b = bh / HEADS;
    const int h = bh - b*HEADS;
    const int row0 = q0 + wid*16 + (lane >> 2);
    #pragma unroll
    for (int nt = 0; nt < 8; nt++) {
        const int d = nt*8 + (lane & 3)*2;
        const size_t i0 = (size_t)(b*SEQ + row0)*INNER + h*DHEAD + d;
        const size_t i1 = (size_t)(b*SEQ + row0 + 8)*INNER + h*DHEAD + d;
        *(__half2*)(g_AOs + i0) =
            __halves2half2(__float2half_rn(o[nt][0]*inv0), __float2half_rn(o[nt][1]*inv0));
        *(__half2*)(g_AOs + i1) =
            __halves2half2(__float2half_rn(o[nt][2]*inv1), __float2half_rn(o[nt][3]*inv1));
    }
}

// ---------------------------------------------------------------------------
// Launch
// ---------------------------------------------------------------------------
extern "C" void kernel_launch(void* const* d_in, const int* in_sizes, int n_in,
                              void* d_out, int out_size)
{
    const float* x     = (const float*)d_in[0];
    const float* w_qkv = (const float*)d_in[1];
    const float* w_out = (const float*)d_in[2];
    const float* b_out = (const float*)d_in[3];
    float* out = (float*)d_out;

    cudaFuncSetAttribute(gemm_tc<0>, cudaFuncAttributeMaxDynamicSharedMemorySize, G_SMEM_BYTES);
    cudaFuncSetAttribute(gemm_tc<1>, cudaFuncAttributeMaxDynamicSharedMemorySize, G_SMEM_BYTES);
    cudaFuncSetAttribute(attn_tc,    cudaFuncAttributeMaxDynamicSharedMemorySize, A_SMEM_BYTES);

    cvt_all<<<(N_X + N_WQ + N_WO)/1024, 256>>>(x, w_qkv, w_out);

    dim3 g1(NQKV/128, MROWS/128);   // 18 x 64
    gemm_tc<0><<<g1, 256, G_SMEM_BYTES>>>(nullptr, nullptr);

    dim3 g2(SEQ/128, BATCH*HEADS);  // 8 x 96
    attn_tc<<<g2, 256, A_SMEM_BYTES>>>();

    dim3 g3(DIM/128, MROWS/128);    // 6 x 64 (M-tile 128 restored)
    gemm_tc<1><<<g3, 256, G_SMEM_BYTES>>>(b_out, out);
}

// round 17
// speedup vs baseline: 1.0921x; 1.0579x over previous
#include <cuda_runtime.h>
#include <cuda_fp16.h>
#include <cstdint>
#include <math.h>

#define BATCH   8
#define SEQ     1024
#define DIM     768
#define HEADS   12
#define DHEAD   64
#define INNER   768
#define NQKV    2304
#define MROWS   8192
#define SC_LOG2E 0.1803368801111244f
#define ONES_H2 0x3C003C00u   // fp16 1.0 x2

// ---------------------------------------------------------------------------
// Persistent fp16 scratch (all single fp16; error budget fixed at ~6.5e-4)
// ---------------------------------------------------------------------------
__device__ __half g_Xs [MROWS*DIM];
__device__ __half g_WQs[DIM*NQKV];
__device__ __half g_WOs[INNER*DIM];
__device__ __half g_Qs [BATCH*HEADS*SEQ*DHEAD];
__device__ __half g_Ks [BATCH*HEADS*SEQ*DHEAD];
__device__ __half g_Vs [BATCH*HEADS*SEQ*DHEAD];
__device__ __half g_AOs[MROWS*INNER];

// ---------------------------------------------------------------------------
// Helpers
// ---------------------------------------------------------------------------
__device__ __forceinline__ uint32_t smem_u32(const void* p) {
    uint32_t a;
    asm("{ .reg .u64 t; cvta.to.shared.u64 t, %1; cvt.u32.u64 %0, t; }" : "=r"(a) : "l"(p));
    return a;
}
__device__ __forceinline__ void ldsm4(uint32_t addr, uint32_t* r) {
    asm volatile("ldmatrix.sync.aligned.m8n8.x4.shared.b16 {%0,%1,%2,%3}, [%4];"
                 : "=r"(r[0]), "=r"(r[1]), "=r"(r[2]), "=r"(r[3]) : "r"(addr));
}
__device__ __forceinline__ void ldsm4t(uint32_t addr, uint32_t* r) {
    asm volatile("ldmatrix.sync.aligned.m8n8.x4.trans.shared.b16 {%0,%1,%2,%3}, [%4];"
                 : "=r"(r[0]), "=r"(r[1]), "=r"(r[2]), "=r"(r[3]) : "r"(addr));
}
__device__ __forceinline__ void mma16816(float* c, const uint32_t* a, uint32_t b0, uint32_t b1) {
    asm volatile("mma.sync.aligned.m16n8k16.row.col.f32.f16.f16.f32 "
                 "{%0,%1,%2,%3}, {%4,%5,%6,%7}, {%8,%9}, {%0,%1,%2,%3};"
                 : "+f"(c[0]), "+f"(c[1]), "+f"(c[2]), "+f"(c[3])
                 : "r"(a[0]), "r"(a[1]), "r"(a[2]), "r"(a[3]), "r"(b0), "r"(b1));
}
__device__ __forceinline__ float fast_exp2(float x) {
    float y;
    asm("ex2.approx.f32 %0, %1;" : "=f"(y) : "f"(x));
    return y;
}
__device__ __forceinline__ void cpa16(uint32_t dst, const void* src) {
    asm volatile("cp.async.cg.shared.global [%0], [%1], 16;" :: "r"(dst), "l"(src));
}
#define CP_COMMIT() asm volatile("cp.async.commit_group;" ::: "memory")
// Wait so that the group for chunk c is complete, given lookahead 2.
#define CP_WAIT_LA2(c, NC) do { \
    if ((c) + 2 < (NC))      asm volatile("cp.async.wait_group 2;" ::: "memory"); \
    else if ((c) + 1 < (NC)) asm volatile("cp.async.wait_group 1;" ::: "memory"); \
    else                     asm volatile("cp.async.wait_group 0;" ::: "memory"); \
} while (0)

__device__ __forceinline__ uint32_t pack_h2(float x, float y) {
    __half2 h = __halves2half2(__float2half_rn(x), __float2half_rn(y));
    return *reinterpret_cast<uint32_t*>(&h);
}

// ---------------------------------------------------------------------------
// Merged pre-convert: fp32 -> fp16 for X, Wqkv, Wout in one launch.
// ---------------------------------------------------------------------------
#define N_X  (MROWS*DIM)
#define N_WQ (DIM*NQKV)
#define N_WO (INNER*DIM)

__global__ void cvt_all(const float* __restrict__ x,
                        const float* __restrict__ wq,
                        const float* __restrict__ wo)
{
    const int i = (blockIdx.x * blockDim.x + threadIdx.x) * 4;
    const float* src;
    __half* dst;
    int j;
    if (i < N_X)                { src = x;  dst = g_Xs;  j = i; }
    else if (i < N_X + N_WQ)    { src = wq; dst = g_WQs; j = i - N_X; }
    else if (i < N_X+N_WQ+N_WO) { src = wo; dst = g_WOs; j = i - N_X - N_WQ; }
    else return;
    float4 v = *(const float4*)(src + j);
    *(__half2*)(dst + j)     = __halves2half2(__float2half_rn(v.x), __float2half_rn(v.y));
    *(__half2*)(dst + j + 2) = __halves2half2(__float2half_rn(v.z), __float2half_rn(v.w));
}

// ---------------------------------------------------------------------------
// GEMM (exact R14 structure — measured best): single-pass fp16, K-chunk 32,
// 4-stage pipeline / lookahead 2, ONE barrier per chunk
// (prefetch -> wait -> barrier -> compute), 2 CTAs/SM, 128x128 tile.
// MODE 0: X @ Wqkv -> Q(scaled)/K/V fp16.  MODE 1: AO @ Wout + bias -> fp32.
// ---------------------------------------------------------------------------
#define G_A   0
#define G_B   10240
#define G_STAGE 18944
#define G_SMEM_BYTES (4*G_STAGE)   // 75776
#define G_NCHUNK 24

template<int MODE>
__global__ void __launch_bounds__(256, 2)
gemm_tc(const float* __restrict__ bias, float* __restrict__ out)
{
    extern __shared__ char smem[];
    const uint32_t sb = smem_u32(smem);
    const int tid  = threadIdx.x;
    const int lane = tid & 31;
    const int wid  = tid >> 5;
    const int wm   = wid & 3;
    const int wn   = wid >> 2;
    const int bx = blockIdx.x, by = blockIdx.y;

    const __half* As = (MODE == 0) ? g_Xs  : g_AOs;
    const __half* Bs = (MODE == 0) ? g_WQs : g_WOs;
    const int ldb = (MODE == 0) ? NQKV : DIM;

    float acc[2][8][4];
    #pragma unroll
    for (int i = 0; i < 2; i++)
        #pragma unroll
        for (int j = 0; j < 8; j++)
            #pragma unroll
            for (int k = 0; k < 4; k++) acc[i][j][k] = 0.f;

    const int lrow = lane & 15;
    const int lc16 = (lane >> 4) * 16;
    const uint32_t aA = sb + G_A + (uint32_t)((wm*32 + lrow)*80) + lc16;
    const uint32_t aB = sb + G_B + (uint32_t)(lrow*272) + (uint32_t)(wn*128) + lc16;

    auto prefetch = [&](int ch, int st) {
        const int k0 = ch * 32;
        const uint32_t sa = sb + (uint32_t)st * G_STAGE;
        #pragma unroll
        for (int i = tid; i < 512; i += 256) {
            const int row = i >> 2, seg = i & 3;
            cpa16(sa + G_A + row*80 + seg*16,
                  As + (size_t)(by*128 + row)*768 + k0 + seg*8);
        }
        #pragma unroll
        for (int i = tid; i < 512; i += 256) {
            const int row = i >> 4, seg = i & 15;
            cpa16(sa + G_B + row*272 + seg*16,
                  Bs + (size_t)(k0 + row)*ldb + bx*128 + seg*8);
        }
    };

    prefetch(0, 0); CP_COMMIT();
    prefetch(1, 1); CP_COMMIT();

    for (int ch = 0; ch < G_NCHUNK; ch++) {
        if (ch + 2 < G_NCHUNK) { prefetch(ch + 2, (ch + 2) & 3); CP_COMMIT(); }
        CP_WAIT_LA2(ch, G_NCHUNK);   // this thread's group ch complete
        __syncthreads();             // ALL threads' group-ch copies now visible

        const uint32_t so = (uint32_t)(ch & 3) * G_STAGE;
        #pragma unroll
        for (int ks = 0; ks < 2; ks++) {
            uint32_t ah[2][4];
            ldsm4(aA + so + ks*32,         ah[0]);
            ldsm4(aA + so + 16*80 + ks*32, ah[1]);
            uint32_t bh[4][4];
            #pragma unroll
            for (int np = 0; np < 4; np++)
                ldsm4t(aB + so + ks*4352 + np*32, bh[np]);
            #pragma unroll
            for (int np = 0; np < 4; np++)
                #pragma unroll
                for (int mt = 0; mt < 2; mt++) {
                    mma16816(acc[mt][np*2+0], ah[mt], bh[np][0], bh[np][1]);
                    mma16816(acc[mt][np*2+1], ah[mt], bh[np][2], bh[np][3]);
                }
        }
    }

    // Epilogue
    #pragma unroll
    for (int mt = 0; mt < 2; mt++) {
        const int row0 = by*128 + wm*32 + mt*16 + (lane >> 2);
        #pragma unroll
        for (int nt = 0; nt < 8; nt++) {
            const int col = bx*128 + wn*64 + nt*8 + (lane & 3)*2;
            if (MODE == 0) {
                const int sel = col / INNER;
                const int cr = col - sel*INNER;
                const int h = cr >> 6, d = cr & 63;
                __half* dst = (sel == 0) ? g_Qs : (sel == 1) ? g_Ks : g_Vs;
                const float sc = (sel == 0) ? SC_LOG2E : 1.f;
                #pragma unroll
                for (int rr = 0; rr < 2; rr++) {
                    const int r = row0 + rr*8;
                    const int b = r >> 10, nn = r & 1023;
                    const size_t idx = (size_t)(((b*HEADS + h) << 10) + nn)*DHEAD + d;
                    *(__half2*)(dst + idx) =
                        __halves2half2(__float2half_rn(acc[mt][nt][rr*2+0]*sc),
                                       __float2half_rn(acc[mt][nt][rr*2+1]*sc));
                }
            } else {
                const float b0 = bias[col], b1 = bias[col+1];
                *(float2*)&out[(size_t)row0*DIM + col] =
                    make_float2(acc[mt][nt][0] + b0, acc[mt][nt][1] + b1);
                *(float2*)&out[(size_t)(row0+8)*DIM + col] =
                    make_float2(acc[mt][nt][2] + b0, acc[mt][nt][3] + b1);
            }
        }
    }
}

// ---------------------------------------------------------------------------
// Attention (R14 structure + hoisted Q fragments): single-pass,
// P-in-registers, rowsum via ones-MMA, 4-stage KV pipeline / lookahead 2,
// ONE barrier per chunk, 2 CTAs/SM. 8 warps x 16 q rows.
// ---------------------------------------------------------------------------
#define A_Q   0
#define A_KV0 18432
#define A_KSo 0
#define A_VSo 9216
#define A_KVSTAGE 18432
#define A_SMEM_BYTES (18432 + 4*A_KVSTAGE)   // 92160
#define A_NCHUNK 16

__global__ void __launch_bounds__(256, 2)
attn_tc()
{
    extern __shared__ char smem[];
    const uint32_t sb = smem_u32(smem);
    const int tid  = threadIdx.x;
    const int lane = tid & 31;
    const int wid  = tid >> 5;
    const int bh = blockIdx.y;
    const int q0 = blockIdx.x * 128;

    const size_t base = (size_t)bh * SEQ * DHEAD;

    auto prefetchKV = [&](int c, int st) {
        const size_t g0 = base + (size_t)c*64*DHEAD;
        const uint32_t sa = sb + A_KV0 + (uint32_t)st * A_KVSTAGE;
        #pragma unroll
        for (int i = tid; i < 512; i += 256) {
            const int row = i >> 3, seg = i & 7;
            const uint32_t d = sa + row*144 + seg*16;
            const size_t g = g0 + row*64 + seg*8;
            cpa16(d + A_KSo, g_Ks + g);
            cpa16(d + A_VSo, g_Vs + g);
        }
    };

    // group 0 = Q + KV chunk 0, group 1 = KV chunk 1
    #pragma unroll
    for (int i = tid; i < 1024; i += 256) {
        const int row = i >> 3, seg = i & 7;
        cpa16(sb + A_Q + row*144 + seg*16,
              g_Qs + base + (size_t)(q0 + row)*DHEAD + seg*8);
    }
    prefetchKV(0, 0); CP_COMMIT();
    prefetchKV(1, 1); CP_COMMIT();

    float o[8][4];
    #pragma unroll
    for (int j = 0; j < 8; j++)
        #pragma unroll
        for (int k = 0; k < 4; k++) o[j][k] = 0.f;
    float rs[4] = {0.f, 0.f, 0.f, 0.f};

    const int lrow = lane & 15;
    const int lc16 = (lane >> 4) * 16;
    const uint32_t aQ = sb + A_Q   + (uint32_t)((wid*16 + lrow)*144) + lc16;
    const uint32_t aK = sb + A_KV0 + A_KSo + (uint32_t)(lrow*144) + lc16;
    const uint32_t aV = sb + A_KV0 + A_VSo + (uint32_t)(lrow*144) + lc16;

    uint32_t qh[4][4];   // hoisted chunk-invariant Q fragments

    for (int c = 0; c < A_NCHUNK; c++) {
        if (c + 2 < A_NCHUNK) { prefetchKV(c + 2, (c + 2) & 3); CP_COMMIT(); }
        CP_WAIT_LA2(c, A_NCHUNK);
        __syncthreads();             // all threads' group-c copies visible

        if (c == 0) {                // Q (group 0) resident now; load once
            #pragma unroll
            for (int ks = 0; ks < 4; ks++)
                ldsm4(aQ + ks*32, qh[ks]);
        }

        const uint32_t so = (uint32_t)(c & 3) * A_KVSTAGE;

        // ---- S = Q @ K^T ----
        float s[8][4];
        #pragma unroll
        for (int j = 0; j < 8; j++)
            #pragma unroll
            for (int k = 0; k < 4; k++) s[j][k] = 0.f;

        #pragma unroll
        for (int ks = 0; ks < 4; ks++) {
            uint32_t kh[4][4];
            #pragma unroll
            for (int np = 0; np < 4; np++)
                ldsm4(aK + so + np*16*144 + ks*32, kh[np]);
            // non-trans pairing: {r0,r2} / {r1,r3}
            #pragma unroll
            for (int np = 0; np < 4; np++) {
                mma16816(s[np*2+0], qh[ks], kh[np][0], kh[np][2]);
                mma16816(s[np*2+1], qh[ks], kh[np][1], kh[np][3]);
            }
        }

        // ---- P = 2^S -> fp16 A-fragments; rowsum via ones-MMA ----
        uint32_t pa[4][4];
        #pragma unroll
        for (int kf = 0; kf < 4; kf++) {
            const int t0 = 2*kf, t1 = 2*kf + 1;
            const float e0 = fast_exp2(s[t0][0]);
            const float e1 = fast_exp2(s[t0][1]);
            const float e2 = fast_exp2(s[t0][2]);
            const float e3 = fast_exp2(s[t0][3]);
            const float f0 = fast_exp2(s[t1][0]);
            const float f1 = fast_exp2(s[t1][1]);
            const float f2 = fast_exp2(s[t1][2]);
            const float f3 = fast_exp2(s[t1][3]);
            pa[kf][0] = pack_h2(e0, e1);
            pa[kf][1] = pack_h2(e2, e3);
            pa[kf][2] = pack_h2(f0, f1);
            pa[kf][3] = pack_h2(f2, f3);
            mma16816(rs, pa[kf], ONES_H2, ONES_H2);
        }

        // ---- O += P @ V ----
        #pragma unroll
        for (int kf = 0; kf < 4; kf++) {
            uint32_t vh[4][4];
            #pragma unroll
            for (int np = 0; np < 4; np++)
                ldsm4t(aV + so + kf*16*144 + np*32, vh[np]);
            // trans pairing: {r0,r1} / {r2,r3}
            #pragma unroll
            for (int np = 0; np < 4; np++) {
                mma16816(o[np*2+0], pa[kf], vh[np][0], vh[np][1]);
                mma16816(o[np*2+1], pa[kf], vh[np][2], vh[np][3]);
            }
        }
    }

    // rs[0] = rowsum(row), rs[2] = rowsum(row+8)
    const float inv0 = 1.f / rs[0];
    const float inv1 = 1.f / rs[2];

    // Normalize + fp16 AO store
    const int b = bh / HEADS;
    const int h = bh - b*HEADS;
    const int row0 = q0 + wid*16 + (lane >> 2);
    #pragma unroll
    for (int nt = 0; nt < 8; nt++) {
        const int d = nt*8 + (lane & 3)*2;
        const size_t i0 = (size_t)(b*SEQ + row0)*INNER + h*DHEAD + d;
        const size_t i1 = (size_t)(b*SEQ + row0 + 8)*INNER + h*DHEAD + d;
        *(__half2*)(g_AOs + i0) =
            __halves2half2(__float2half_rn(o[nt][0]*inv0), __float2half_rn(o[nt][1]*inv0));
        *(__half2*)(g_AOs + i1) =
            __halves2half2(__float2half_rn(o[nt][2]*inv1), __float2half_rn(o[nt][3]*inv1));
    }
}

// ---------------------------------------------------------------------------
// Launch
// ---------------------------------------------------------------------------
extern "C" void kernel_launch(void* const* d_in, const int* in_sizes, int n_in,
                              void* d_out, int out_size)
{
    const float* x     = (const float*)d_in[0];
    const float* w_qkv = (const float*)d_in[1];
    const float* w_out = (const float*)d_in[2];
    const float* b_out = (const float*)d_in[3];
    float* out = (float*)d_out;

    cudaFuncSetAttribute(gemm_tc<0>, cudaFuncAttributeMaxDynamicSharedMemorySize, G_SMEM_BYTES);
    cudaFuncSetAttribute(gemm_tc<1>, cudaFuncAttributeMaxDynamicSharedMemorySize, G_SMEM_BYTES);
    cudaFuncSetAttribute(attn_tc,    cudaFuncAttributeMaxDynamicSharedMemorySize, A_SMEM_BYTES);

    cvt_all<<<(N_X + N_WQ + N_WO)/1024, 256>>>(x, w_qkv, w_out);

    dim3 g1(NQKV/128, MROWS/128);   // 18 x 64
    gemm_tc<0><<<g1, 256, G_SMEM_BYTES>>>(nullptr, nullptr);

    dim3 g2(SEQ/128, BATCH*HEADS);  // 8 x 96
    attn_tc<<<g2, 256, A_SMEM_BYTES>>>();

    dim3 g3(DIM/128, MROWS/128);    // 6 x 64
    gemm_tc<1><<<g3, 256, G_SMEM_BYTES>>>(b_out, out);
}